// round 14
// baseline (speedup 1.0000x reference)
#include <cuda_runtime.h>
#include <cuda_bf16.h>
#include <math.h>
#include <stdint.h>

#define N_NODES 50000
#define N_EDGES 500000
#define IN_C    128
#define HID_C   256
#define OUT_C   64
#define CAP     64                             // fixed row bucket capacity
#define EDGE_BLOCKS ((N_EDGES + 255) / 256)    // 1954
#define INITF_BLOCKS ((N_NODES * IN_C / 4 + 255) / 256)  // 6250
#define CONV_TOTAL (IN_C * HID_C + HID_C * HID_C + HID_C * OUT_C)  // 114688
#define CONV_BLOCKS ((CONV_TOTAL + 255) / 256) // 448
#define SPMM_BLOCKS 1184
#define SPMM_WARPS  (SPMM_BLOCKS * 8)
#define GEMM_BLOCKS 296                        // 148 SMs x 2 CTA/SM, persistent

// ===================== scratch (static device globals) ======================
__device__ int   g_cnt[N_NODES];     // INVARIANT: zero at kernel_launch entry
__device__ int   g_col[(size_t)N_NODES * CAP];
__device__ float g_bufF[(size_t)N_NODES * IN_C];
__device__ float g_bufA[(size_t)N_NODES * IN_C];
__device__ float g_bufB[(size_t)N_NODES * IN_C];
__device__ __nv_bfloat16 g_a2y [(size_t)N_NODES * (2 * IN_C)];
__device__ __nv_bfloat16 g_h12 [(size_t)N_NODES * (2 * HID_C)];
__device__ __nv_bfloat16 g_h22 [(size_t)N_NODES * (2 * HID_C)];
__device__ __nv_bfloat16 g_wt1 [(size_t)HID_C * (3 * IN_C)];
__device__ __nv_bfloat16 g_wt2 [(size_t)HID_C * (3 * HID_C)];
__device__ __nv_bfloat16 g_wt3 [(size_t)OUT_C * (3 * HID_C)];

// ===================== small helpers ========================================
__device__ __forceinline__ uint32_t smem_u32(const void* p) {
    uint32_t a;
    asm("{ .reg .u64 t; cvta.to.shared.u64 t, %1; cvt.u32.u64 %0, t; }" : "=r"(a) : "l"(p));
    return a;
}
__device__ __forceinline__ uint32_t pack_hi2(float a, float b, float& la, float& lb) {
    __nv_bfloat16 ah = __float2bfloat16(a);
    __nv_bfloat16 bh = __float2bfloat16(b);
    la = a - __bfloat162float(ah);
    lb = b - __bfloat162float(bh);
    __nv_bfloat162 h2; h2.x = ah; h2.y = bh;
    return *(uint32_t*)&h2;
}
__device__ __forceinline__ uint32_t pack_bf2(float a, float b) {
    __nv_bfloat162 h2; h2.x = __float2bfloat16(a); h2.y = __float2bfloat16(b);
    return *(uint32_t*)&h2;
}
__device__ __forceinline__ void ldsm_x4(uint32_t (&r)[4], uint32_t addr) {
    asm volatile("ldmatrix.sync.aligned.m8n8.x4.shared.b16 {%0,%1,%2,%3},[%4];"
                 : "=r"(r[0]), "=r"(r[1]), "=r"(r[2]), "=r"(r[3]) : "r"(addr));
}
__device__ __forceinline__ void ldsm_x2(uint32_t (&r)[2], uint32_t addr) {
    asm volatile("ldmatrix.sync.aligned.m8n8.x2.shared.b16 {%0,%1},[%2];"
                 : "=r"(r[0]), "=r"(r[1]) : "r"(addr));
}
__device__ __forceinline__ void mma_bf16(float (&d)[4], const uint32_t (&a)[4],
                                         uint32_t b0, uint32_t b1) {
    asm volatile("mma.sync.aligned.m16n8k16.row.col.f32.bf16.bf16.f32 "
                 "{%0,%1,%2,%3},{%4,%5,%6,%7},{%8,%9},{%0,%1,%2,%3};"
                 : "+f"(d[0]), "+f"(d[1]), "+f"(d[2]), "+f"(d[3])
                 : "r"(a[0]), "r"(a[1]), "r"(a[2]), "r"(a[3]), "r"(b0), "r"(b1));
}
__device__ __forceinline__ void cp16(uint32_t dst, const void* src, int sz) {
    asm volatile("cp.async.cg.shared.global [%0],[%1],16,%2;"
                 :: "r"(dst), "l"(src), "r"(sz) : "memory");
}
__device__ __forceinline__ void cp16(uint32_t dst, const void* src) {
    asm volatile("cp.async.cg.shared.global [%0],[%1],16;"
                 :: "r"(dst), "l"(src) : "memory");
}
#define CP_COMMIT() asm volatile("cp.async.commit_group;" ::: "memory")
#define CP_WAITG(n) asm volatile("cp.async.wait_group %0;" :: "n"(n) : "memory")

// ===================== launch 0: fill buckets + init f + convw ==============
__device__ __forceinline__ void conv_one(const float* __restrict__ W,
                                         __nv_bfloat16* __restrict__ Wt3,
                                         int K, int N, int i) {
    int k = i / N, n = i % N;
    float v = W[i];
    __nv_bfloat16 hi = __float2bfloat16(v);
    __nv_bfloat16 lo = __float2bfloat16(v - __bfloat162float(hi));
    size_t rb = (size_t)n * 3 * K;
    Wt3[rb + k]         = hi;
    Wt3[rb + K + k]     = hi;
    Wt3[rb + 2 * K + k] = lo;
}

__global__ void prologue_kernel(const int* __restrict__ ei, const float* __restrict__ x,
                                const float* __restrict__ W1, const float* __restrict__ W2,
                                const float* __restrict__ W3) {
    int b = blockIdx.x;
    if (b < EDGE_BLOCKS) {
        // direct bucket fill (g_cnt zero on entry, invariant)
        int e = b * 256 + threadIdx.x;
        if (e < N_EDGES) {
            int s = ei[e];
            int d = ei[N_EDGES + e];
            int p = atomicAdd(&g_cnt[s], 1);
            if (p < CAP) g_col[(size_t)s * CAP + p] = d;
        }
    } else if (b < EDGE_BLOCKS + INITF_BLOCKS) {
        int i = (b - EDGE_BLOCKS) * 256 + threadIdx.x;
        if (i < N_NODES * IN_C / 4) {
            float4 v = ((const float4*)x)[i];
            v.x *= 0.5f; v.y *= 0.5f; v.z *= 0.5f; v.w *= 0.5f;
            ((float4*)g_bufF)[i] = v;
        }
    } else {
        int i = (b - EDGE_BLOCKS - INITF_BLOCKS) * 256 + threadIdx.x;
        const int n1 = IN_C * HID_C;
        const int n2 = n1 + HID_C * HID_C;
        if (i < n1)              conv_one(W1, g_wt1, IN_C,  HID_C, i);
        else if (i < n2)         conv_one(W2, g_wt2, HID_C, HID_C, i - n1);
        else if (i < CONV_TOTAL) conv_one(W3, g_wt3, HID_C, OUT_C, i - n2);
    }
}

// ===================== launches 1..5: SpMM (Horner) =========================
template <bool EMIT>
__global__ void __launch_bounds__(256) spmm_kernel(const float* __restrict__ tin,
                                                   float* __restrict__ tout) {
    int w0 = (blockIdx.x * blockDim.x + threadIdx.x) >> 5;
    int lane = threadIdx.x & 31;
    for (int row = w0; row < N_NODES; row += SPMM_WARPS) {
        int len = g_cnt[row];
        if (len > CAP) len = CAP;
        const int* cols = g_col + (size_t)row * CAP;
        float4 acc = *(const float4*)(g_bufF + (size_t)row * IN_C + lane * 4);
        int idx = 0;
        for (; idx + 3 < len; idx += 4) {
            int j0 = cols[idx];
            int j1 = cols[idx + 1];
            int j2 = cols[idx + 2];
            int j3 = cols[idx + 3];
            float4 v0 = *(const float4*)(tin + (size_t)j0 * IN_C + lane * 4);
            float4 v1 = *(const float4*)(tin + (size_t)j1 * IN_C + lane * 4);
            float4 v2 = *(const float4*)(tin + (size_t)j2 * IN_C + lane * 4);
            float4 v3 = *(const float4*)(tin + (size_t)j3 * IN_C + lane * 4);
            acc.x += (v0.x + v1.x) + (v2.x + v3.x);
            acc.y += (v0.y + v1.y) + (v2.y + v3.y);
            acc.z += (v0.z + v1.z) + (v2.z + v3.z);
            acc.w += (v0.w + v1.w) + (v2.w + v3.w);
        }
        for (; idx < len; ++idx) {
            int j = cols[idx];
            float4 v = *(const float4*)(tin + (size_t)j * IN_C + lane * 4);
            acc.x += v.x; acc.y += v.y; acc.z += v.z; acc.w += v.w;
        }
        if (!EMIT) {
            *(float4*)(tout + (size_t)row * IN_C + lane * 4) = acc;
        } else {
            const float sc = 1.0f / 6.0f;
            float a = acc.x * sc, b = acc.y * sc, c = acc.z * sc, d = acc.w * sc;
            float la, lb, lc, ld;
            uint2 h2, l2;
            h2.x = pack_hi2(a, b, la, lb);
            h2.y = pack_hi2(c, d, lc, ld);
            l2.x = pack_bf2(la, lb);
            l2.y = pack_bf2(lc, ld);
            __nv_bfloat16* orow = g_a2y + (size_t)row * (2 * IN_C);
            int c0 = lane * 4;
            *(uint2*)(orow + c0)        = h2;
            *(uint2*)(orow + IN_C + c0) = l2;
        }
    }
}

// ===================== GEMM1/2: persistent, BK=64, 3-stage, warp 64x32 ======
template <int LOGK, int APHYS>
__global__ void __launch_bounds__(256, 2) mgemmP_kernel(
    const __nv_bfloat16* __restrict__ A2, const __nv_bfloat16* __restrict__ Bt3,
    const float* __restrict__ bias, __nv_bfloat16* __restrict__ outb)
{
    constexpr int NK = LOGK / 64;
    constexpr int AROWB = 144;               // 64 bf16 + 16B pad
    constexpr int A_STRIDE = 128 * AROWB;    // 18432
    constexpr int B_STRIDE = 128 * AROWB;
    constexpr int NTILES = 391 * 2;

    extern __shared__ __align__(16) unsigned char smem[];
    __shared__ float sbias[128];

    const int t = threadIdx.x;
    const int lane = t & 31;
    const int wid = t >> 5;
    const int wm = wid & 1;
    const int wn = wid >> 1;

    const uint32_t smA_addr = smem_u32(smem);
    const uint32_t smB_addr = smA_addr + 3 * A_STRIDE;

    for (int tile = blockIdx.x; tile < NTILES; tile += GEMM_BLOCKS) {
        const int m0 = (tile >> 1) * 128;
        const int n0 = (tile & 1) * 128;

        float acc[4][4][4];
#pragma unroll
        for (int mi = 0; mi < 4; ++mi)
#pragma unroll
            for (int ni = 0; ni < 4; ++ni)
#pragma unroll
                for (int q = 0; q < 4; ++q) acc[mi][ni][q] = 0.f;

        auto load_tile = [&](int kbase, int s) {
            const int kphys = (kbase >= APHYS) ? (kbase - APHYS) : kbase;
#pragma unroll
            for (int i = 0; i < 4; ++i) {
                int u = t + i * 256;
                int row = u >> 3, seg = u & 7;
                uint32_t dst = smA_addr + s * A_STRIDE + row * AROWB + seg * 16;
                int m = m0 + row;
                int mc = (m < N_NODES) ? m : 0;
                const __nv_bfloat16* src = A2 + (size_t)mc * APHYS + kphys + seg * 8;
                cp16(dst, src, (m < N_NODES) ? 16 : 0);
            }
#pragma unroll
            for (int i = 0; i < 4; ++i) {
                int u = t + i * 256;
                int row = u >> 3, seg = u & 7;
                uint32_t dst = smB_addr + s * B_STRIDE + row * AROWB + seg * 16;
                const __nv_bfloat16* src = Bt3 + (size_t)(n0 + row) * LOGK + kbase + seg * 8;
                cp16(dst, src);
            }
        };

        load_tile(0, 0);
        CP_COMMIT();
        load_tile(64, 1);
        CP_COMMIT();

        for (int kt = 0; kt < NK; ++kt) {
            if (kt == NK - 1) { CP_WAITG(0); } else { CP_WAITG(1); }
            __syncthreads();
            if (kt == 0 && t < 128) sbias[t] = bias[n0 + t];
            if (kt + 2 < NK) {
                load_tile((kt + 2) * 64, (kt + 2) % 3);
                CP_COMMIT();
            }
            const int s = kt % 3;
            const uint32_t abase = smA_addr + s * A_STRIDE +
                                   (wm * 64 + (lane & 15)) * AROWB + ((lane >> 4) * 16);
            const uint32_t bbase = smB_addr + s * B_STRIDE +
                                   (wn * 32 + (lane & 15)) * AROWB + ((lane >> 4) * 16);
#pragma unroll
            for (int h = 0; h < 4; ++h) {
                uint32_t aF[4][4];
                uint32_t bQ[2][4];
#pragma unroll
                for (int mi = 0; mi < 4; ++mi)
                    ldsm_x4(aF[mi], abase + h * 32 + mi * 16 * AROWB);
                ldsm_x4(bQ[0], bbase + h * 32);
                ldsm_x4(bQ[1], bbase + h * 32 + 16 * AROWB);
#pragma unroll
                for (int mi = 0; mi < 4; ++mi)
#pragma unroll
                    for (int nq = 0; nq < 2; ++nq) {
                        mma_bf16(acc[mi][2 * nq + 0], aF[mi], bQ[nq][0], bQ[nq][2]);
                        mma_bf16(acc[mi][2 * nq + 1], aF[mi], bQ[nq][1], bQ[nq][3]);
                    }
            }
        }

        const int lr = lane >> 2;
        const int lc = (lane & 3) * 2;
#pragma unroll
        for (int mi = 0; mi < 4; ++mi) {
#pragma unroll
            for (int half = 0; half < 2; ++half) {
                const int m = m0 + wm * 64 + mi * 16 + lr + half * 8;
                if (m < N_NODES) {
                    __nv_bfloat16* orow = outb + (size_t)m * (2 * HID_C);
#pragma unroll
                    for (int ni = 0; ni < 4; ++ni) {
                        int cl = wn * 32 + ni * 8 + lc;
                        float a = acc[mi][ni][half * 2 + 0] + sbias[cl];
                        float b = acc[mi][ni][half * 2 + 1] + sbias[cl + 1];
                        a = fmaxf(a, 0.f); b = fmaxf(b, 0.f);
                        float la, lb;
                        uint32_t hi = pack_hi2(a, b, la, lb);
                        uint32_t lo = pack_bf2(la, lb);
                        int col = n0 + cl;
                        *(uint32_t*)(orow + col)         = hi;
                        *(uint32_t*)(orow + HID_C + col) = lo;
                    }
                }
            }
        }
        __syncthreads();
    }
}

// ===================== GEMM3 (N=64): persistent, BK=64 + log-softmax ========
// Also restores the g_cnt=0 invariant for the next kernel_launch call.
__global__ void __launch_bounds__(256, 2) mgemm3_kernel(
    const __nv_bfloat16* __restrict__ A2, const __nv_bfloat16* __restrict__ Bt3,
    const float* __restrict__ bias, float* __restrict__ outf)
{
    constexpr int LOGK = 768, APHYS = 512, N_TILE = 64;
    constexpr int NK = LOGK / 64;
    constexpr int NI = 4;
    constexpr int WTN = 32;
    constexpr int AROWB = 144;
    constexpr int A_STRIDE = 128 * AROWB;
    constexpr int B_STRIDE = N_TILE * AROWB;
    constexpr int NTILES = (N_NODES + 127) / 128;  // 391

    extern __shared__ __align__(16) unsigned char smem[];
    __shared__ float sbias[N_TILE];

    const int t = threadIdx.x;
    const int lane = t & 31;
    const int wid = t >> 5;
    const int wm = wid & 3;
    const int wn = wid >> 2;

    // restore invariant: zero g_cnt (cnt is no longer read this call)
    for (int i = blockIdx.x * 256 + t; i < N_NODES; i += GEMM_BLOCKS * 256)
        g_cnt[i] = 0;

    const uint32_t smA_addr = smem_u32(smem);
    const uint32_t smB_addr = smA_addr + 3 * A_STRIDE;

    for (int tile = blockIdx.x; tile < NTILES; tile += GEMM_BLOCKS) {
        const int m0 = tile * 128;

        float acc[2][NI][4];
#pragma unroll
        for (int mi = 0; mi < 2; ++mi)
#pragma unroll
            for (int ni = 0; ni < NI; ++ni)
#pragma unroll
                for (int q = 0; q < 4; ++q) acc[mi][ni][q] = 0.f;

        auto load_tile = [&](int kbase, int s) {
            const int kphys = (kbase >= APHYS) ? (kbase - APHYS) : kbase;
#pragma unroll
            for (int i = 0; i < 4; ++i) {
                int u = t + i * 256;
                int row = u >> 3, seg = u & 7;
                uint32_t dst = smA_addr + s * A_STRIDE + row * AROWB + seg * 16;
                int m = m0 + row;
                int mc = (m < N_NODES) ? m : 0;
                const __nv_bfloat16* src = A2 + (size_t)mc * APHYS + kphys + seg * 8;
                cp16(dst, src, (m < N_NODES) ? 16 : 0);
            }
#pragma unroll
            for (int i = 0; i < 2; ++i) {
                int u = t + i * 256;
                int row = u >> 3, seg = u & 7;
                uint32_t dst = smB_addr + s * B_STRIDE + row * AROWB + seg * 16;
                const __nv_bfloat16* src = Bt3 + (size_t)row * LOGK + kbase + seg * 8;
                cp16(dst, src);
            }
        };

        load_tile(0, 0);
        CP_COMMIT();
        load_tile(64, 1);
        CP_COMMIT();

        for (int kt = 0; kt < NK; ++kt) {
            if (kt == NK - 1) { CP_WAITG(0); } else { CP_WAITG(1); }
            __syncthreads();
            if (kt == 0 && t < N_TILE) sbias[t] = bias[t];
            if (kt + 2 < NK) {
                load_tile((kt + 2) * 64, (kt + 2) % 3);
                CP_COMMIT();
            }
            const int s = kt % 3;
            const uint32_t abase0 = smA_addr + s * A_STRIDE +
                                    (wm * 32 + (lane & 15)) * AROWB + ((lane >> 4) * 16);
            const uint32_t bbase0 = smB_addr + s * B_STRIDE +
                                    (wn * WTN + (lane & 7)) * AROWB + (((lane >> 3) & 1) * 16);
#pragma unroll
            for (int h = 0; h < 4; ++h) {
                uint32_t aF[2][4];
                uint32_t bF[NI][2];
                ldsm_x4(aF[0], abase0 + h * 32);
                ldsm_x4(aF[1], abase0 + h * 32 + 16 * AROWB);
#pragma unroll
                for (int ni = 0; ni < NI; ++ni)
                    ldsm_x2(bF[ni], bbase0 + h * 32 + ni * 8 * AROWB);
#pragma unroll
                for (int mi = 0; mi < 2; ++mi)
#pragma unroll
                    for (int ni = 0; ni < NI; ++ni)
                        mma_bf16(acc[mi][ni], aF[mi], bF[ni][0], bF[ni][1]);
            }
        }

        const int lr = lane >> 2;
        const int lc = (lane & 3) * 2;
        float* slog = (float*)smem;
        __syncthreads();
#pragma unroll
        for (int mi = 0; mi < 2; ++mi) {
#pragma unroll
            for (int half = 0; half < 2; ++half) {
                const int r = wm * 32 + mi * 16 + lr + half * 8;
#pragma unroll
                for (int ni = 0; ni < NI; ++ni) {
                    int cl = wn * WTN + ni * 8 + lc;
                    float a = acc[mi][ni][half * 2 + 0] + sbias[cl];
                    float b = acc[mi][ni][half * 2 + 1] + sbias[cl + 1];
                    *(float2*)(slog + r * 66 + cl) = make_float2(a, b);
                }
            }
        }
        __syncthreads();
#pragma unroll
        for (int rr = 0; rr < 16; ++rr) {
            int r = wid * 16 + rr;
            int m = m0 + r;
            float v0 = slog[r * 66 + lane];
            float v1 = slog[r * 66 + lane + 32];
            float mx = fmaxf(v0, v1);
#pragma unroll
            for (int off = 16; off > 0; off >>= 1)
                mx = fmaxf(mx, __shfl_xor_sync(0xFFFFFFFFu, mx, off));
            float sm = expf(v0 - mx) + expf(v1 - mx);
#pragma unroll
            for (int off = 16; off > 0; off >>= 1)
                sm += __shfl_xor_sync(0xFFFFFFFFu, sm, off);
            float l = mx + logf(sm);
            if (m < N_NODES) {
                outf[(size_t)m * 64 + lane]      = v0 - l;
                outf[(size_t)m * 64 + lane + 32] = v1 - l;
            }
        }
        __syncthreads();
    }
}

// ===================== launch ===============================================
extern "C" void kernel_launch(void* const* d_in, const int* in_sizes, int n_in,
                              void* d_out, int out_size) {
    const float* x  = (const float*)d_in[0];
    const int*   ei = (const int*)  d_in[1];
    const float* W1 = (const float*)d_in[2];
    const float* b1 = (const float*)d_in[3];
    const float* W2 = (const float*)d_in[4];
    const float* b2 = (const float*)d_in[5];
    const float* W3 = (const float*)d_in[6];
    const float* b3 = (const float*)d_in[7];
    float* out = (float*)d_out;
    (void)in_sizes; (void)n_in; (void)out_size;

    void *pF, *pA, *pB, *pa2, *ph12, *ph22, *pw1, *pw2, *pw3;
    cudaGetSymbolAddress(&pF,  g_bufF);
    cudaGetSymbolAddress(&pA,  g_bufA);
    cudaGetSymbolAddress(&pB,  g_bufB);
    cudaGetSymbolAddress(&pa2, g_a2y);
    cudaGetSymbolAddress(&ph12, g_h12);
    cudaGetSymbolAddress(&ph22, g_h22);
    cudaGetSymbolAddress(&pw1, g_wt1);
    cudaGetSymbolAddress(&pw2, g_wt2);
    cudaGetSymbolAddress(&pw3, g_wt3);
    float* bufF = (float*)pF;
    float* bufA = (float*)pA;
    float* bufB = (float*)pB;
    __nv_bfloat16* a2y = (__nv_bfloat16*)pa2;
    __nv_bfloat16* h12 = (__nv_bfloat16*)ph12;
    __nv_bfloat16* h22 = (__nv_bfloat16*)ph22;
    __nv_bfloat16* wt1 = (__nv_bfloat16*)pw1;
    __nv_bfloat16* wt2 = (__nv_bfloat16*)pw2;
    __nv_bfloat16* wt3 = (__nv_bfloat16*)pw3;

    const int smemP  = 3 * (128 * 144) + 3 * (128 * 144);   // 110592
    const int smem3a = 3 * (128 * 144) + 3 * (64 * 144);    // 82944
    const int smem3b = 128 * 66 * 4;                        // 33792
    const int smem3  = (smem3a > smem3b) ? smem3a : smem3b;
    cudaFuncSetAttribute((const void*)mgemmP_kernel<384, 256>,
                         cudaFuncAttributeMaxDynamicSharedMemorySize, smemP);
    cudaFuncSetAttribute((const void*)mgemmP_kernel<768, 512>,
                         cudaFuncAttributeMaxDynamicSharedMemorySize, smemP);
    cudaFuncSetAttribute((const void*)mgemm3_kernel,
                         cudaFuncAttributeMaxDynamicSharedMemorySize, smem3);

    // 0: bucket fill (cnt pre-zeroed invariant) + f init + weight conversion
    prologue_kernel<<<EDGE_BLOCKS + INITF_BLOCKS + CONV_BLOCKS, 256>>>(ei, x, W1, W2, W3);

    // 1..5: Horner propagation (index 3 = profiled spmm hop)
    spmm_kernel<false><<<SPMM_BLOCKS, 256>>>(bufF, bufA);
    spmm_kernel<false><<<SPMM_BLOCKS, 256>>>(bufA, bufB);
    spmm_kernel<false><<<SPMM_BLOCKS, 256>>>(bufB, bufA);
    spmm_kernel<false><<<SPMM_BLOCKS, 256>>>(bufA, bufB);
    spmm_kernel<true><<<SPMM_BLOCKS, 256>>>(bufB, bufA);

    // 6..8: persistent GEMMs (GEMM3 restores g_cnt invariant)
    mgemmP_kernel<384, 256><<<GEMM_BLOCKS, 256, smemP>>>(a2y, wt1, b1, h12);
    mgemmP_kernel<768, 512><<<GEMM_BLOCKS, 256, smemP>>>(h12, wt2, b2, h22);
    mgemm3_kernel<<<GEMM_BLOCKS, 256, smem3>>>(h22, wt3, b3, out);
}

// round 15
// speedup vs baseline: 1.0473x; 1.0473x over previous
#include <cuda_runtime.h>
#include <cuda_bf16.h>
#include <math.h>
#include <stdint.h>

#define N_NODES 50000
#define N_EDGES 500000
#define IN_C    128
#define HID_C   256
#define OUT_C   64
#define SCAN_BLOCKS ((N_NODES + 255) / 256)   // 196
#define EDGE_BLOCKS ((N_EDGES + 255) / 256)   // 1954
#define INITF_BLOCKS ((N_NODES * IN_C / 4 + 255) / 256)  // 6250
#define CONV_TOTAL (IN_C * HID_C + HID_C * HID_C + HID_C * OUT_C)  // 114688
#define CONV_BLOCKS ((CONV_TOTAL + 255) / 256) // 448
#define SPMM_BLOCKS 1184
#define SPMM_WARPS  (SPMM_BLOCKS * 8)
#define GEMM_BLOCKS 296                        // 148 SMs x 2 CTA/SM, persistent

// ===================== scratch (static device globals) ======================
__device__ int   g_cnt[N_NODES];     // INVARIANT: zero at kernel_launch entry
__device__ int   g_rp [N_NODES];
__device__ int   g_wp [N_NODES];
__device__ int   g_ctr;              // INVARIANT: zero at entry
__device__ int   g_col[N_EDGES];
__device__ float g_bufF[(size_t)N_NODES * IN_C];
__device__ float g_bufA[(size_t)N_NODES * IN_C];
__device__ float g_bufB[(size_t)N_NODES * IN_C];
__device__ __nv_bfloat16 g_a2y [(size_t)N_NODES * (2 * IN_C)];
__device__ __nv_bfloat16 g_h12 [(size_t)N_NODES * (2 * HID_C)];
__device__ __nv_bfloat16 g_h22 [(size_t)N_NODES * (2 * HID_C)];
__device__ __nv_bfloat16 g_wt1 [(size_t)HID_C * (3 * IN_C)];
__device__ __nv_bfloat16 g_wt2 [(size_t)HID_C * (3 * HID_C)];
__device__ __nv_bfloat16 g_wt3 [(size_t)OUT_C * (3 * HID_C)];

// ===================== small helpers ========================================
__device__ __forceinline__ uint32_t smem_u32(const void* p) {
    uint32_t a;
    asm("{ .reg .u64 t; cvta.to.shared.u64 t, %1; cvt.u32.u64 %0, t; }" : "=r"(a) : "l"(p));
    return a;
}
__device__ __forceinline__ uint32_t pack_hi2(float a, float b, float& la, float& lb) {
    __nv_bfloat16 ah = __float2bfloat16(a);
    __nv_bfloat16 bh = __float2bfloat16(b);
    la = a - __bfloat162float(ah);
    lb = b - __bfloat162float(bh);
    __nv_bfloat162 h2; h2.x = ah; h2.y = bh;
    return *(uint32_t*)&h2;
}
__device__ __forceinline__ uint32_t pack_bf2(float a, float b) {
    __nv_bfloat162 h2; h2.x = __float2bfloat16(a); h2.y = __float2bfloat16(b);
    return *(uint32_t*)&h2;
}
__device__ __forceinline__ void ldsm_x4(uint32_t (&r)[4], uint32_t addr) {
    asm volatile("ldmatrix.sync.aligned.m8n8.x4.shared.b16 {%0,%1,%2,%3},[%4];"
                 : "=r"(r[0]), "=r"(r[1]), "=r"(r[2]), "=r"(r[3]) : "r"(addr));
}
__device__ __forceinline__ void ldsm_x2(uint32_t (&r)[2], uint32_t addr) {
    asm volatile("ldmatrix.sync.aligned.m8n8.x2.shared.b16 {%0,%1},[%2];"
                 : "=r"(r[0]), "=r"(r[1]) : "r"(addr));
}
__device__ __forceinline__ void mma_bf16(float (&d)[4], const uint32_t (&a)[4],
                                         uint32_t b0, uint32_t b1) {
    asm volatile("mma.sync.aligned.m16n8k16.row.col.f32.bf16.bf16.f32 "
                 "{%0,%1,%2,%3},{%4,%5,%6,%7},{%8,%9},{%0,%1,%2,%3};"
                 : "+f"(d[0]), "+f"(d[1]), "+f"(d[2]), "+f"(d[3])
                 : "r"(a[0]), "r"(a[1]), "r"(a[2]), "r"(a[3]), "r"(b0), "r"(b1));
}
__device__ __forceinline__ void cp16(uint32_t dst, const void* src, int sz) {
    asm volatile("cp.async.cg.shared.global [%0],[%1],16,%2;"
                 :: "r"(dst), "l"(src), "r"(sz) : "memory");
}
__device__ __forceinline__ void cp16(uint32_t dst, const void* src) {
    asm volatile("cp.async.cg.shared.global [%0],[%1],16;"
                 :: "r"(dst), "l"(src) : "memory");
}
#define CP_COMMIT() asm volatile("cp.async.commit_group;" ::: "memory")
#define CP_WAITG(n) asm volatile("cp.async.wait_group %0;" :: "n"(n) : "memory")

// ===================== launch 0: hist + init f + convw (independent) ========
__device__ __forceinline__ void conv_one(const float* __restrict__ W,
                                         __nv_bfloat16* __restrict__ Wt3,
                                         int K, int N, int i) {
    int k = i / N, n = i % N;
    float v = W[i];
    __nv_bfloat16 hi = __float2bfloat16(v);
    __nv_bfloat16 lo = __float2bfloat16(v - __bfloat162float(hi));
    size_t rb = (size_t)n * 3 * K;
    Wt3[rb + k]         = hi;
    Wt3[rb + K + k]     = hi;
    Wt3[rb + 2 * K + k] = lo;
}

__global__ void prologue_kernel(const int* __restrict__ ei, const float* __restrict__ x,
                                const float* __restrict__ W1, const float* __restrict__ W2,
                                const float* __restrict__ W3) {
    int b = blockIdx.x;
    if (b < EDGE_BLOCKS) {
        int e = b * 256 + threadIdx.x;
        if (e < N_EDGES) atomicAdd(&g_cnt[ei[e]], 1);
    } else if (b < EDGE_BLOCKS + INITF_BLOCKS) {
        int i = (b - EDGE_BLOCKS) * 256 + threadIdx.x;
        if (i < N_NODES * IN_C / 4) {
            float4 v = ((const float4*)x)[i];
            v.x *= 0.5f; v.y *= 0.5f; v.z *= 0.5f; v.w *= 0.5f;
            ((float4*)g_bufF)[i] = v;
        }
    } else {
        int i = (b - EDGE_BLOCKS - INITF_BLOCKS) * 256 + threadIdx.x;
        const int n1 = IN_C * HID_C;
        const int n2 = n1 + HID_C * HID_C;
        if (i < n1)              conv_one(W1, g_wt1, IN_C,  HID_C, i);
        else if (i < n2)         conv_one(W2, g_wt2, HID_C, HID_C, i - n1);
        else if (i < CONV_TOTAL) conv_one(W3, g_wt3, HID_C, OUT_C, i - n2);
    }
}

// ===================== launch 1: order-free bucket allocation ===============
__global__ void scanA_kernel() {
    int b = blockIdx.x, t = threadIdx.x;
    int i = b * 256 + t;
    int lane = t & 31, w = t >> 5;
    int v = (i < N_NODES) ? g_cnt[i] : 0;
    int x = v;
#pragma unroll
    for (int o = 1; o < 32; o <<= 1) {
        int y = __shfl_up_sync(0xFFFFFFFFu, x, o);
        if (lane >= o) x += y;
    }
    __shared__ int ws[8];
    __shared__ int sbase;
    if (lane == 31) ws[w] = x;
    __syncthreads();
    if (w == 0 && lane < 8) {
        int y = ws[lane];
#pragma unroll
        for (int o = 1; o < 8; o <<= 1) {
            int z = __shfl_up_sync(0xFFu, y, o);
            if (lane >= o) y += z;
        }
        ws[lane] = y;
    }
    __syncthreads();
    int incl = x + (w > 0 ? ws[w - 1] : 0);
    if (t == 255) sbase = atomicAdd(&g_ctr, incl);
    __syncthreads();
    if (i < N_NODES) {
        int st = sbase + incl - v;
        g_rp[i] = st;
        g_wp[i] = st;
    }
}

// ===================== launch 2: fill =======================================
__global__ void fill_kernel(const int* __restrict__ ei) {
    int e = blockIdx.x * blockDim.x + threadIdx.x;
    if (e < N_EDGES) {
        int s = ei[e];
        int d = ei[N_EDGES + e];
        int p = atomicAdd(&g_wp[s], 1);
        g_col[p] = d;
    }
}

// ===================== launches 3..7: SpMM (Horner) =========================
template <bool EMIT>
__global__ void __launch_bounds__(256) spmm_kernel(const float* __restrict__ tin,
                                                   float* __restrict__ tout) {
    int w0 = (blockIdx.x * blockDim.x + threadIdx.x) >> 5;
    int lane = threadIdx.x & 31;
    for (int row = w0; row < N_NODES; row += SPMM_WARPS) {
        int s = g_rp[row];
        int e = s + g_cnt[row];
        float4 acc = *(const float4*)(g_bufF + (size_t)row * IN_C + lane * 4);
        int idx = s;
        for (; idx + 3 < e; idx += 4) {
            int j0 = g_col[idx];
            int j1 = g_col[idx + 1];
            int j2 = g_col[idx + 2];
            int j3 = g_col[idx + 3];
            float4 v0 = *(const float4*)(tin + (size_t)j0 * IN_C + lane * 4);
            float4 v1 = *(const float4*)(tin + (size_t)j1 * IN_C + lane * 4);
            float4 v2 = *(const float4*)(tin + (size_t)j2 * IN_C + lane * 4);
            float4 v3 = *(const float4*)(tin + (size_t)j3 * IN_C + lane * 4);
            acc.x += (v0.x + v1.x) + (v2.x + v3.x);
            acc.y += (v0.y + v1.y) + (v2.y + v3.y);
            acc.z += (v0.z + v1.z) + (v2.z + v3.z);
            acc.w += (v0.w + v1.w) + (v2.w + v3.w);
        }
        for (; idx < e; ++idx) {
            int j = g_col[idx];
            float4 v = *(const float4*)(tin + (size_t)j * IN_C + lane * 4);
            acc.x += v.x; acc.y += v.y; acc.z += v.z; acc.w += v.w;
        }
        if (!EMIT) {
            *(float4*)(tout + (size_t)row * IN_C + lane * 4) = acc;
        } else {
            const float sc = 1.0f / 6.0f;
            float a = acc.x * sc, b = acc.y * sc, c = acc.z * sc, d = acc.w * sc;
            float la, lb, lc, ld;
            uint2 h2, l2;
            h2.x = pack_hi2(a, b, la, lb);
            h2.y = pack_hi2(c, d, lc, ld);
            l2.x = pack_bf2(la, lb);
            l2.y = pack_bf2(lc, ld);
            __nv_bfloat16* orow = g_a2y + (size_t)row * (2 * IN_C);
            int c0 = lane * 4;
            *(uint2*)(orow + c0)        = h2;
            *(uint2*)(orow + IN_C + c0) = l2;
        }
    }
}

// ===================== GEMM1/2: persistent, BK=64, 3-stage, warp 64x32 ======
template <int LOGK, int APHYS>
__global__ void __launch_bounds__(256, 2) mgemmP_kernel(
    const __nv_bfloat16* __restrict__ A2, const __nv_bfloat16* __restrict__ Bt3,
    const float* __restrict__ bias, __nv_bfloat16* __restrict__ outb)
{
    constexpr int NK = LOGK / 64;
    constexpr int AROWB = 144;               // 64 bf16 + 16B pad
    constexpr int A_STRIDE = 128 * AROWB;    // 18432
    constexpr int B_STRIDE = 128 * AROWB;
    constexpr int NTILES = 391 * 2;

    extern __shared__ __align__(16) unsigned char smem[];
    __shared__ float sbias[128];

    const int t = threadIdx.x;
    const int lane = t & 31;
    const int wid = t >> 5;
    const int wm = wid & 1;
    const int wn = wid >> 1;

    const uint32_t smA_addr = smem_u32(smem);
    const uint32_t smB_addr = smA_addr + 3 * A_STRIDE;

    for (int tile = blockIdx.x; tile < NTILES; tile += GEMM_BLOCKS) {
        const int m0 = (tile >> 1) * 128;
        const int n0 = (tile & 1) * 128;

        float acc[4][4][4];
#pragma unroll
        for (int mi = 0; mi < 4; ++mi)
#pragma unroll
            for (int ni = 0; ni < 4; ++ni)
#pragma unroll
                for (int q = 0; q < 4; ++q) acc[mi][ni][q] = 0.f;

        auto load_tile = [&](int kbase, int s) {
            const int kphys = (kbase >= APHYS) ? (kbase - APHYS) : kbase;
#pragma unroll
            for (int i = 0; i < 4; ++i) {
                int u = t + i * 256;
                int row = u >> 3, seg = u & 7;
                uint32_t dst = smA_addr + s * A_STRIDE + row * AROWB + seg * 16;
                int m = m0 + row;
                int mc = (m < N_NODES) ? m : 0;
                const __nv_bfloat16* src = A2 + (size_t)mc * APHYS + kphys + seg * 8;
                cp16(dst, src, (m < N_NODES) ? 16 : 0);
            }
#pragma unroll
            for (int i = 0; i < 4; ++i) {
                int u = t + i * 256;
                int row = u >> 3, seg = u & 7;
                uint32_t dst = smB_addr + s * B_STRIDE + row * AROWB + seg * 16;
                const __nv_bfloat16* src = Bt3 + (size_t)(n0 + row) * LOGK + kbase + seg * 8;
                cp16(dst, src);
            }
        };

        load_tile(0, 0);
        CP_COMMIT();
        load_tile(64, 1);
        CP_COMMIT();

        for (int kt = 0; kt < NK; ++kt) {
            if (kt == NK - 1) { CP_WAITG(0); } else { CP_WAITG(1); }
            __syncthreads();
            if (kt == 0 && t < 128) sbias[t] = bias[n0 + t];
            if (kt + 2 < NK) {
                load_tile((kt + 2) * 64, (kt + 2) % 3);
                CP_COMMIT();
            }
            const int s = kt % 3;
            const uint32_t abase = smA_addr + s * A_STRIDE +
                                   (wm * 64 + (lane & 15)) * AROWB + ((lane >> 4) * 16);
            const uint32_t bbase = smB_addr + s * B_STRIDE +
                                   (wn * 32 + (lane & 15)) * AROWB + ((lane >> 4) * 16);
#pragma unroll
            for (int h = 0; h < 4; ++h) {
                uint32_t aF[4][4];
                uint32_t bQ[2][4];
#pragma unroll
                for (int mi = 0; mi < 4; ++mi)
                    ldsm_x4(aF[mi], abase + h * 32 + mi * 16 * AROWB);
                ldsm_x4(bQ[0], bbase + h * 32);
                ldsm_x4(bQ[1], bbase + h * 32 + 16 * AROWB);
#pragma unroll
                for (int mi = 0; mi < 4; ++mi)
#pragma unroll
                    for (int nq = 0; nq < 2; ++nq) {
                        mma_bf16(acc[mi][2 * nq + 0], aF[mi], bQ[nq][0], bQ[nq][2]);
                        mma_bf16(acc[mi][2 * nq + 1], aF[mi], bQ[nq][1], bQ[nq][3]);
                    }
            }
        }

        const int lr = lane >> 2;
        const int lc = (lane & 3) * 2;
#pragma unroll
        for (int mi = 0; mi < 4; ++mi) {
#pragma unroll
            for (int half = 0; half < 2; ++half) {
                const int m = m0 + wm * 64 + mi * 16 + lr + half * 8;
                if (m < N_NODES) {
                    __nv_bfloat16* orow = outb + (size_t)m * (2 * HID_C);
#pragma unroll
                    for (int ni = 0; ni < 4; ++ni) {
                        int cl = wn * 32 + ni * 8 + lc;
                        float a = acc[mi][ni][half * 2 + 0] + sbias[cl];
                        float b = acc[mi][ni][half * 2 + 1] + sbias[cl + 1];
                        a = fmaxf(a, 0.f); b = fmaxf(b, 0.f);
                        float la, lb;
                        uint32_t hi = pack_hi2(a, b, la, lb);
                        uint32_t lo = pack_bf2(la, lb);
                        int col = n0 + cl;
                        *(uint32_t*)(orow + col)         = hi;
                        *(uint32_t*)(orow + HID_C + col) = lo;
                    }
                }
            }
        }
        __syncthreads();
    }
}

// ===================== GEMM3 (N=64): persistent, BK=64 + log-softmax ========
// Also restores the g_cnt=0 / g_ctr=0 invariants for the next call.
__global__ void __launch_bounds__(256, 2) mgemm3_kernel(
    const __nv_bfloat16* __restrict__ A2, const __nv_bfloat16* __restrict__ Bt3,
    const float* __restrict__ bias, float* __restrict__ outf)
{
    constexpr int LOGK = 768, APHYS = 512, N_TILE = 64;
    constexpr int NK = LOGK / 64;
    constexpr int NI = 4;
    constexpr int WTN = 32;
    constexpr int AROWB = 144;
    constexpr int A_STRIDE = 128 * AROWB;
    constexpr int B_STRIDE = N_TILE * AROWB;
    constexpr int NTILES = (N_NODES + 127) / 128;  // 391

    extern __shared__ __align__(16) unsigned char smem[];
    __shared__ float sbias[N_TILE];

    const int t = threadIdx.x;
    const int lane = t & 31;
    const int wid = t >> 5;
    const int wm = wid & 3;
    const int wn = wid >> 2;

    // restore invariants (cnt/ctr no longer read this call)
    for (int i = blockIdx.x * 256 + t; i < N_NODES; i += GEMM_BLOCKS * 256)
        g_cnt[i] = 0;
    if (blockIdx.x == 0 && t == 0) g_ctr = 0;

    const uint32_t smA_addr = smem_u32(smem);
    const uint32_t smB_addr = smA_addr + 3 * A_STRIDE;

    for (int tile = blockIdx.x; tile < NTILES; tile += GEMM_BLOCKS) {
        const int m0 = tile * 128;

        float acc[2][NI][4];
#pragma unroll
        for (int mi = 0; mi < 2; ++mi)
#pragma unroll
            for (int ni = 0; ni < NI; ++ni)
#pragma unroll
                for (int q = 0; q < 4; ++q) acc[mi][ni][q] = 0.f;

        auto load_tile = [&](int kbase, int s) {
            const int kphys = (kbase >= APHYS) ? (kbase - APHYS) : kbase;
#pragma unroll
            for (int i = 0; i < 4; ++i) {
                int u = t + i * 256;
                int row = u >> 3, seg = u & 7;
                uint32_t dst = smA_addr + s * A_STRIDE + row * AROWB + seg * 16;
                int m = m0 + row;
                int mc = (m < N_NODES) ? m : 0;
                const __nv_bfloat16* src = A2 + (size_t)mc * APHYS + kphys + seg * 8;
                cp16(dst, src, (m < N_NODES) ? 16 : 0);
            }
#pragma unroll
            for (int i = 0; i < 2; ++i) {
                int u = t + i * 256;
                int row = u >> 3, seg = u & 7;
                uint32_t dst = smB_addr + s * B_STRIDE + row * AROWB + seg * 16;
                const __nv_bfloat16* src = Bt3 + (size_t)row * LOGK + kbase + seg * 8;
                cp16(dst, src);
            }
        };

        load_tile(0, 0);
        CP_COMMIT();
        load_tile(64, 1);
        CP_COMMIT();

        for (int kt = 0; kt < NK; ++kt) {
            if (kt == NK - 1) { CP_WAITG(0); } else { CP_WAITG(1); }
            __syncthreads();
            if (kt == 0 && t < N_TILE) sbias[t] = bias[t];
            if (kt + 2 < NK) {
                load_tile((kt + 2) * 64, (kt + 2) % 3);
                CP_COMMIT();
            }
            const int s = kt % 3;
            const uint32_t abase0 = smA_addr + s * A_STRIDE +
                                    (wm * 32 + (lane & 15)) * AROWB + ((lane >> 4) * 16);
            const uint32_t bbase0 = smB_addr + s * B_STRIDE +
                                    (wn * WTN + (lane & 7)) * AROWB + (((lane >> 3) & 1) * 16);
#pragma unroll
            for (int h = 0; h < 4; ++h) {
                uint32_t aF[2][4];
                uint32_t bF[NI][2];
                ldsm_x4(aF[0], abase0 + h * 32);
                ldsm_x4(aF[1], abase0 + h * 32 + 16 * AROWB);
#pragma unroll
                for (int ni = 0; ni < NI; ++ni)
                    ldsm_x2(bF[ni], bbase0 + h * 32 + ni * 8 * AROWB);
#pragma unroll
                for (int mi = 0; mi < 2; ++mi)
#pragma unroll
                    for (int ni = 0; ni < NI; ++ni)
                        mma_bf16(acc[mi][ni], aF[mi], bF[ni][0], bF[ni][1]);
            }
        }

        const int lr = lane >> 2;
        const int lc = (lane & 3) * 2;
        float* slog = (float*)smem;
        __syncthreads();
#pragma unroll
        for (int mi = 0; mi < 2; ++mi) {
#pragma unroll
            for (int half = 0; half < 2; ++half) {
                const int r = wm * 32 + mi * 16 + lr + half * 8;
#pragma unroll
                for (int ni = 0; ni < NI; ++ni) {
                    int cl = wn * WTN + ni * 8 + lc;
                    float a = acc[mi][ni][half * 2 + 0] + sbias[cl];
                    float b = acc[mi][ni][half * 2 + 1] + sbias[cl + 1];
                    *(float2*)(slog + r * 66 + cl) = make_float2(a, b);
                }
            }
        }
        __syncthreads();
#pragma unroll
        for (int rr = 0; rr < 16; ++rr) {
            int r = wid * 16 + rr;
            int m = m0 + r;
            float v0 = slog[r * 66 + lane];
            float v1 = slog[r * 66 + lane + 32];
            float mx = fmaxf(v0, v1);
#pragma unroll
            for (int off = 16; off > 0; off >>= 1)
                mx = fmaxf(mx, __shfl_xor_sync(0xFFFFFFFFu, mx, off));
            float sm = expf(v0 - mx) + expf(v1 - mx);
#pragma unroll
            for (int off = 16; off > 0; off >>= 1)
                sm += __shfl_xor_sync(0xFFFFFFFFu, sm, off);
            float l = mx + logf(sm);
            if (m < N_NODES) {
                outf[(size_t)m * 64 + lane]      = v0 - l;
                outf[(size_t)m * 64 + lane + 32] = v1 - l;
            }
        }
        __syncthreads();
    }
}

// ===================== launch ===============================================
extern "C" void kernel_launch(void* const* d_in, const int* in_sizes, int n_in,
                              void* d_out, int out_size) {
    const float* x  = (const float*)d_in[0];
    const int*   ei = (const int*)  d_in[1];
    const float* W1 = (const float*)d_in[2];
    const float* b1 = (const float*)d_in[3];
    const float* W2 = (const float*)d_in[4];
    const float* b2 = (const float*)d_in[5];
    const float* W3 = (const float*)d_in[6];
    const float* b3 = (const float*)d_in[7];
    float* out = (float*)d_out;
    (void)in_sizes; (void)n_in; (void)out_size;

    void *pF, *pA, *pB, *pa2, *ph12, *ph22, *pw1, *pw2, *pw3;
    cudaGetSymbolAddress(&pF,  g_bufF);
    cudaGetSymbolAddress(&pA,  g_bufA);
    cudaGetSymbolAddress(&pB,  g_bufB);
    cudaGetSymbolAddress(&pa2, g_a2y);
    cudaGetSymbolAddress(&ph12, g_h12);
    cudaGetSymbolAddress(&ph22, g_h22);
    cudaGetSymbolAddress(&pw1, g_wt1);
    cudaGetSymbolAddress(&pw2, g_wt2);
    cudaGetSymbolAddress(&pw3, g_wt3);
    float* bufF = (float*)pF;
    float* bufA = (float*)pA;
    float* bufB = (float*)pB;
    __nv_bfloat16* a2y = (__nv_bfloat16*)pa2;
    __nv_bfloat16* h12 = (__nv_bfloat16*)ph12;
    __nv_bfloat16* h22 = (__nv_bfloat16*)ph22;
    __nv_bfloat16* wt1 = (__nv_bfloat16*)pw1;
    __nv_bfloat16* wt2 = (__nv_bfloat16*)pw2;
    __nv_bfloat16* wt3 = (__nv_bfloat16*)pw3;

    const int smemP  = 3 * (128 * 144) + 3 * (128 * 144);   // 110592
    const int smem3a = 3 * (128 * 144) + 3 * (64 * 144);    // 82944
    const int smem3b = 128 * 66 * 4;                        // 33792
    const int smem3  = (smem3a > smem3b) ? smem3a : smem3b;
    cudaFuncSetAttribute((const void*)mgemmP_kernel<384, 256>,
                         cudaFuncAttributeMaxDynamicSharedMemorySize, smemP);
    cudaFuncSetAttribute((const void*)mgemmP_kernel<768, 512>,
                         cudaFuncAttributeMaxDynamicSharedMemorySize, smemP);
    cudaFuncSetAttribute((const void*)mgemm3_kernel,
                         cudaFuncAttributeMaxDynamicSharedMemorySize, smem3);

    // 0: hist (cnt pre-zeroed invariant) + f init + weight conversion (fused)
    prologue_kernel<<<EDGE_BLOCKS + INITF_BLOCKS + CONV_BLOCKS, 256>>>(ei, x, W1, W2, W3);
    // 1: bucket allocation, 2: fill
    scanA_kernel<<<SCAN_BLOCKS, 256>>>();
    fill_kernel<<<EDGE_BLOCKS, 256>>>(ei);

    // 3..7: Horner propagation (index 3 = profiled spmm hop)
    spmm_kernel<false><<<SPMM_BLOCKS, 256>>>(bufF, bufA);
    spmm_kernel<false><<<SPMM_BLOCKS, 256>>>(bufA, bufB);
    spmm_kernel<false><<<SPMM_BLOCKS, 256>>>(bufB, bufA);
    spmm_kernel<false><<<SPMM_BLOCKS, 256>>>(bufA, bufB);
    spmm_kernel<true><<<SPMM_BLOCKS, 256>>>(bufB, bufA);

    // 8..10: persistent GEMMs (GEMM3 restores cnt/ctr invariants)
    mgemmP_kernel<384, 256><<<GEMM_BLOCKS, 256, smemP>>>(a2y, wt1, b1, h12);
    mgemmP_kernel<768, 512><<<GEMM_BLOCKS, 256, smemP>>>(h12, wt2, b2, h22);
    mgemm3_kernel<<<GEMM_BLOCKS, 256, smem3>>>(h22, wt3, b3, out);
}